// round 7
// baseline (speedup 1.0000x reference)
#include <cuda_runtime.h>
#include <cuda_bf16.h>

// Problem dims
#define BATCH 256
#define HID   512
#define SEQ   250
#define INDIM 5

// Step-kernel tiling: 128 CTAs = 2 batch groups (M=128) x 64 hidden slices (HC=8 -> N=32 gate cols)
#define GRID_STEP    128
#define THREADS_STEP 128
#define HC 8
#define NC 32          // 4 gates * HC

// SMEM pitches (elements) chosen for conflict-free fragment loads
#define APITCH 520     // bf16 elements per A row (512 + 8)
#define BPITCH 516     // f32 elements per B row (512 + 4)

#define SA_BYTES (128 * APITCH * 2)            // 133120
#define SB_BYTES (NC * BPITCH * 4)             // 66048
#define SX_BYTES (128 * INDIM * 4)             // 2560
#define SWIH_BYTES (NC * INDIM * 4)            // 640
#define SBIAS_BYTES (NC * 4)                   // 128
#define SMEM_BYTES (SA_BYTES + SB_BYTES + SX_BYTES + SWIH_BYTES + SBIAS_BYTES) // 202496

// Persistent state (device globals: no allocation in kernel_launch)
__device__ __nv_bfloat16 g_h[2][BATCH * HID];
__device__ float         g_c[BATCH * HID];

__device__ __forceinline__ float sigmf_(float x) { return 1.0f / (1.0f + expf(-x)); }
__device__ __forceinline__ unsigned f2u(float f) { return __float_as_uint(f); }

// Round fp32 -> tf32 (round-to-nearest) keeping the 32-bit container
__device__ __forceinline__ float cvt_tf32(float f) {
    unsigned r;
    asm("cvt.rna.tf32.f32 %0, %1;" : "=r"(r) : "f"(f));
    return __uint_as_float(r);
}

__device__ __forceinline__ void mma_tf32(float* c, const unsigned* a, unsigned b0, unsigned b1) {
    asm volatile(
        "mma.sync.aligned.m16n8k8.row.col.f32.tf32.tf32.f32 "
        "{%0,%1,%2,%3}, {%4,%5,%6,%7}, {%8,%9}, {%0,%1,%2,%3};"
        : "+f"(c[0]), "+f"(c[1]), "+f"(c[2]), "+f"(c[3])
        : "r"(a[0]), "r"(a[1]), "r"(a[2]), "r"(a[3]), "r"(b0), "r"(b1));
}

__global__ void zero_state_kernel() {
    int i = blockIdx.x * blockDim.x + threadIdx.x;
    if (i < BATCH * HID) {
        g_c[i] = 0.0f;
        g_h[0][i] = __float2bfloat16(0.0f);
    }
}

// One LSTM timestep: gates = (b_ih + b_hh) + x_t @ W_ih^T + h @ W_hh^T, then state update.
// CTA (p, q): batch rows [p*128, p*128+128), hidden units [q*8, q*8+8) (all 4 gates).
__global__ __launch_bounds__(THREADS_STEP)
void lstm_step_kernel(const float* __restrict__ strokes,
                      const float* __restrict__ W_ih,
                      const float* __restrict__ W_hh,
                      const float* __restrict__ b_ih,
                      const float* __restrict__ b_hh,
                      int t, int hsel) {
    extern __shared__ char smem[];
    __nv_bfloat16* sA   = (__nv_bfloat16*)smem;                         // [128][APITCH] bf16 h tile
    float*         sB   = (float*)(smem + SA_BYTES);                    // [32][BPITCH]  tf32 W rows
    float*         sx   = (float*)(smem + SA_BYTES + SB_BYTES);         // [128][5]      x_t tile
    float*         swih = sx + 128 * INDIM;                             // [32][5]
    float*         sbias = swih + NC * INDIM;                           // [32]

    const int tid = threadIdx.x;
    const int q = blockIdx.x & 63;
    const int p = blockIdx.x >> 6;
    const int rowBase = p * 128;
    const int jBase = q * HC;

    const __nv_bfloat16* __restrict__ hin = g_h[hsel] + rowBase * HID;  // contiguous 128 rows
    __nv_bfloat16* __restrict__ hout = g_h[hsel ^ 1];

    // ---- Load A: 128 x 512 bf16 (128 KB), vectorized 16B ----
    {
        const uint4* hin4 = (const uint4*)hin;  // 64 uint4 per row
        #pragma unroll
        for (int it = 0; it < 64; it++) {
            int idx = tid + it * 128;
            int r = idx >> 6, c = idx & 63;
            uint4 v = hin4[idx];
            *(uint4*)(sA + r * APITCH + c * 8) = v;
        }
    }
    // ---- Load B: 32 gate-rows of W_hh (each 512 f32), tf32-rounded ----
    #pragma unroll
    for (int it = 0; it < 32; it++) {
        int idx = tid + it * 128;
        int n = idx >> 7, c = idx & 127;               // 128 float4 per row
        int gate = n >> 3, j = n & 7;
        const float4* src = (const float4*)(W_hh + (size_t)(gate * HID + jBase + j) * HID);
        float4 v = src[c];
        v.x = cvt_tf32(v.x); v.y = cvt_tf32(v.y); v.z = cvt_tf32(v.z); v.w = cvt_tf32(v.w);
        *(float4*)(sB + n * BPITCH + c * 4) = v;
    }
    // ---- x_t tile, W_ih slice, fused biases ----
    for (int idx = tid; idx < 128 * INDIM; idx += THREADS_STEP) {
        int r = idx / INDIM, i = idx - r * INDIM;
        sx[idx] = strokes[(size_t)(rowBase + r) * (SEQ * INDIM) + t * INDIM + i];
    }
    if (tid < NC) {
        int gate = tid >> 3, j = tid & 7;
        int gr = gate * HID + jBase + j;
        sbias[tid] = b_ih[gr] + b_hh[gr];
        #pragma unroll
        for (int i = 0; i < INDIM; i++) swih[tid * INDIM + i] = W_ih[gr * INDIM + i];
    }
    __syncthreads();

    // ---- MMA mainloop: each warp M=32 (2 m-tiles), N=32 (4 n-tiles), K=512 ----
    const int warp = tid >> 5, lane = tid & 31;
    const int g4 = lane >> 2, tg = lane & 3;

    float acc[2][4][4];
    #pragma unroll
    for (int a = 0; a < 2; a++)
        #pragma unroll
        for (int b = 0; b < 4; b++)
            #pragma unroll
            for (int c = 0; c < 4; c++) acc[a][b][c] = 0.0f;

    const __nv_bfloat16* A0 = sA + (warp * 32 + g4) * APITCH;
    const float* Bb = sB + g4 * BPITCH;

    #pragma unroll 4
    for (int ks = 0; ks < 64; ks++) {
        const int k0 = ks * 8;
        unsigned a[2][4];
        #pragma unroll
        for (int mt = 0; mt < 2; mt++) {
            const __nv_bfloat16* r0 = A0 + mt * 16 * APITCH + k0;
            const __nv_bfloat16* r1 = r0 + 8 * APITCH;
            // bf16 -> f32 is exact and a valid tf32 operand (<=8 mantissa bits)
            a[mt][0] = f2u(__bfloat162float(r0[tg]));
            a[mt][1] = f2u(__bfloat162float(r1[tg]));
            a[mt][2] = f2u(__bfloat162float(r0[tg + 4]));
            a[mt][3] = f2u(__bfloat162float(r1[tg + 4]));
        }
        #pragma unroll
        for (int nt = 0; nt < 4; nt++) {
            const float* bp = Bb + nt * 8 * BPITCH + k0;
            unsigned b0 = f2u(bp[tg]);
            unsigned b1 = f2u(bp[tg + 4]);
            mma_tf32(acc[0][nt], a[0], b0, b1);
            mma_tf32(acc[1][nt], a[1], b0, b1);
        }
    }

    // ---- Epilogue: each thread owns all 4 gates for its (row, j) pairs -> local update ----
    // C frag (m16n8): elem0 (row g4, col 2tg), elem1 (g4, 2tg+1), elem2 (g4+8, 2tg), elem3 (g4+8, 2tg+1)
    #pragma unroll
    for (int mt = 0; mt < 2; mt++) {
        #pragma unroll
        for (int half = 0; half < 2; half++) {
            int rloc = warp * 32 + mt * 16 + g4 + half * 8;
            int grow = rowBase + rloc;
            #pragma unroll
            for (int bb = 0; bb < 2; bb++) {
                int e = half * 2 + bb;
                int j = tg * 2 + bb;
                float xs[4];
                #pragma unroll
                for (int gate = 0; gate < 4; gate++) {
                    int n = gate * 8 + j;
                    float s = sbias[n];
                    #pragma unroll
                    for (int i = 0; i < INDIM; i++) s += sx[rloc * INDIM + i] * swih[n * INDIM + i];
                    xs[gate] = s;
                }
                float iv = acc[mt][0][e] + xs[0];
                float fv = acc[mt][1][e] + xs[1];
                float gv = acc[mt][2][e] + xs[2];
                float ov = acc[mt][3][e] + xs[3];
                int cidx = grow * HID + jBase + j;
                float cn = sigmf_(fv) * g_c[cidx] + sigmf_(iv) * tanhf(gv);
                g_c[cidx] = cn;
                hout[cidx] = __float2bfloat16(sigmf_(ov) * tanhf(cn));
            }
        }
    }
}

// out[b] = sigmoid(leaky_relu(h_final . W_out + b_out, 0.1))
__global__ void head_kernel(const float* __restrict__ W_out,
                            const float* __restrict__ b_out,
                            float* __restrict__ out) {
    int b = blockIdx.x;
    int lane = threadIdx.x;
    float s = 0.0f;
    #pragma unroll
    for (int j = lane; j < HID; j += 32)
        s += __bfloat162float(g_h[0][b * HID + j]) * W_out[j];  // SEQ even -> final h in buffer 0
    #pragma unroll
    for (int o = 16; o; o >>= 1) s += __shfl_xor_sync(0xffffffffu, s, o);
    if (lane == 0) {
        float raw = s + b_out[0];
        float lr = raw > 0.0f ? raw : 0.1f * raw;
        out[b] = 1.0f / (1.0f + expf(-lr));
    }
}

extern "C" void kernel_launch(void* const* d_in, const int* in_sizes, int n_in,
                              void* d_out, int out_size) {
    const float* strokes = (const float*)d_in[0];
    const float* W_ih    = (const float*)d_in[1];
    const float* W_hh    = (const float*)d_in[2];
    const float* b_ih    = (const float*)d_in[3];
    const float* b_hh    = (const float*)d_in[4];
    const float* W_out   = (const float*)d_in[5];
    const float* b_out   = (const float*)d_in[6];
    float* out = (float*)d_out;

    cudaFuncSetAttribute(lstm_step_kernel,
                         cudaFuncAttributeMaxDynamicSharedMemorySize, SMEM_BYTES);

    zero_state_kernel<<<(BATCH * HID + 255) / 256, 256>>>();
    for (int t = 0; t < SEQ; t++) {
        lstm_step_kernel<<<GRID_STEP, THREADS_STEP, SMEM_BYTES>>>(
            strokes, W_ih, W_hh, b_ih, b_hh, t, t & 1);
    }
    head_kernel<<<BATCH, 32>>>(W_out, b_out, out);
}

// round 8
// speedup vs baseline: 1.4689x; 1.4689x over previous
#include <cuda_runtime.h>
#include <cuda_bf16.h>
#include <cstdint>

// Problem dims
#define BATCH 256
#define HID   512
#define SEQ   250
#define INDIM 5

// Persistent tiling: 128 CTAs = 2 batch groups (M=128) x 64 hidden slices (HC=8 -> N=32 gate cols)
#define GRID  128
#define NT    256          // 8 warps, M=16 rows per warp
#define HC 8
#define NC 32              // 4 gates * HC

// SMEM pitches (elements) chosen for conflict-free fragment loads
#define APITCH 520         // bf16 elements per A row (512 + 8)
#define BPITCH 516         // f32 elements per B row (512 + 4)

#define SA_BYTES (128 * APITCH * 2)            // 133120
#define SB_BYTES (NC * BPITCH * 4)             // 66048
#define SX_BYTES (128 * INDIM * 4)             // 2560
#define SWIH_BYTES (NC * INDIM * 4)            // 640
#define SBIAS_BYTES (NC * 4)                   // 128
#define SMEM_BYTES (SA_BYTES + SB_BYTES + SX_BYTES + SWIH_BYTES + SBIAS_BYTES) // 202496

// Persistent state (device globals: no allocation in kernel_launch)
__device__ __nv_bfloat16 g_h[2][BATCH * HID];
__device__ unsigned g_arrive;
__device__ unsigned g_gen;

__device__ __forceinline__ float sigmf_(float x) { return 1.0f / (1.0f + expf(-x)); }
__device__ __forceinline__ unsigned f2u(float f) { return __float_as_uint(f); }

__device__ __forceinline__ float cvt_tf32(float f) {
    unsigned r;
    asm("cvt.rna.tf32.f32 %0, %1;" : "=r"(r) : "f"(f));
    return __uint_as_float(r);
}

__device__ __forceinline__ void mma_tf32(float* c, const unsigned* a, unsigned b0, unsigned b1) {
    asm volatile(
        "mma.sync.aligned.m16n8k8.row.col.f32.tf32.tf32.f32 "
        "{%0,%1,%2,%3}, {%4,%5,%6,%7}, {%8,%9}, {%0,%1,%2,%3};"
        : "+f"(c[0]), "+f"(c[1]), "+f"(c[2]), "+f"(c[3])
        : "r"(a[0]), "r"(a[1]), "r"(a[2]), "r"(a[3]), "r"(b0), "r"(b1));
}

// cp.async: .cg (16B, L1-bypass) for h tiles — REQUIRED for cross-SM coherence of
// the ping-pong h buffers (L1 is not coherent; .cg reads straight from L2).
__device__ __forceinline__ void cp_async16(uint32_t dst, const void* src) {
    asm volatile("cp.async.cg.shared.global [%0], [%1], 16;\n" :: "r"(dst), "l"(src));
}
__device__ __forceinline__ void cp_async4(uint32_t dst, const void* src) {
    asm volatile("cp.async.ca.shared.global [%0], [%1], 4;\n" :: "r"(dst), "l"(src));
}

__global__ void init_kernel() {
    g_arrive = 0u;
    g_gen = 0u;
}

__global__ __launch_bounds__(NT)
void lstm_persistent_kernel(const float* __restrict__ strokes,
                            const float* __restrict__ W_ih,
                            const float* __restrict__ W_hh,
                            const float* __restrict__ b_ih,
                            const float* __restrict__ b_hh,
                            const float* __restrict__ W_out,
                            const float* __restrict__ b_out,
                            float* __restrict__ out) {
    extern __shared__ char smem[];
    __nv_bfloat16* sA    = (__nv_bfloat16*)smem;                          // [128][APITCH] bf16 h tile
    float*         sB    = (float*)(smem + SA_BYTES);                     // [32][BPITCH]  tf32 W rows
    float*         sx    = (float*)(smem + SA_BYTES + SB_BYTES);          // [128][5]      x_t tile
    float*         swih  = sx + 128 * INDIM;                              // [32][5]
    float*         sbias = swih + NC * INDIM;                             // [32]

    const int tid = threadIdx.x;
    const int q = blockIdx.x & 63;
    const int p = blockIdx.x >> 6;
    const int rowBase = p * 128;
    const int jBase = q * HC;

    // ---- One-time: load W_hh slice (tf32-rounded), W_ih slice, fused biases ----
    #pragma unroll
    for (int it = 0; it < 16; it++) {
        int idx = tid + it * NT;                        // 4096 float4 total
        int n = idx >> 7, c = idx & 127;
        int gate = n >> 3, j = n & 7;
        const float4* src = (const float4*)(W_hh + (size_t)(gate * HID + jBase + j) * HID);
        float4 v = src[c];
        v.x = cvt_tf32(v.x); v.y = cvt_tf32(v.y); v.z = cvt_tf32(v.z); v.w = cvt_tf32(v.w);
        *(float4*)(sB + n * BPITCH + c * 4) = v;
    }
    if (tid < NC) {
        int gate = tid >> 3, j = tid & 7;
        int gr = gate * HID + jBase + j;
        sbias[tid] = b_ih[gr] + b_hh[gr];
        #pragma unroll
        for (int i = 0; i < INDIM; i++) swih[tid * INDIM + i] = W_ih[gr * INDIM + i];
    }
    __syncthreads();

    const uint32_t sa_base = (uint32_t)__cvta_generic_to_shared(sA);
    const uint32_t sx_base = (uint32_t)__cvta_generic_to_shared(sx);

    const int warp = tid >> 5, lane = tid & 31;
    const int g4 = lane >> 2, tg = lane & 3;
    const int band = warp * 16;                          // this warp's 16-row M band

    // c state lives in registers: thread owns (row = band+g4+8*half, j = 2*tg+bb)
    float c_reg[2][2] = {{0.0f, 0.0f}, {0.0f, 0.0f}};

    for (int t = 0; t < SEQ; ++t) {
        const __nv_bfloat16* __restrict__ hin = g_h[t & 1] + rowBase * HID;
        __nv_bfloat16* __restrict__ hout = g_h[(t & 1) ^ 1];

        // ---- Stage A (h broadcast) in two K-chunks + x tile, via cp.async ----
        if (t > 0) {
            const uint4* hin4 = (const uint4*)hin;       // [128 rows][64 uint4]
            #pragma unroll
            for (int it = 0; it < 16; it++) {            // chunk0: cols k 0..255
                int idx = tid + it * NT;
                int r = idx >> 5, cq = idx & 31;
                cp_async16(sa_base + (uint32_t)(r * APITCH + cq * 8) * 2, hin4 + r * 64 + cq);
            }
            asm volatile("cp.async.commit_group;\n");
            #pragma unroll
            for (int it = 0; it < 16; it++) {            // chunk1: cols k 256..511
                int idx = tid + it * NT;
                int r = idx >> 5, cq = (idx & 31) + 32;
                cp_async16(sa_base + (uint32_t)(r * APITCH + cq * 8) * 2, hin4 + r * 64 + cq);
            }
        }
        for (int idx = tid; idx < 128 * INDIM; idx += NT) {
            int r = idx / INDIM, i = idx - r * INDIM;
            cp_async4(sx_base + (uint32_t)idx * 4,
                      strokes + (size_t)(rowBase + r) * (SEQ * INDIM) + t * INDIM + i);
        }
        asm volatile("cp.async.commit_group;\n");

        float acc[4][4];
        #pragma unroll
        for (int a = 0; a < 4; a++)
            #pragma unroll
            for (int b = 0; b < 4; b++) acc[a][b] = 0.0f;

        if (t > 0) {
            const __nv_bfloat16* A0 = sA + (band + g4) * APITCH;
            const float* Bb = sB + g4 * BPITCH;

            asm volatile("cp.async.wait_group 1;\n");    // chunk0 landed
            __syncthreads();
            #pragma unroll 4
            for (int ks = 0; ks < 32; ks++) {            // mma over k 0..255 while chunk1 streams
                const int k0 = ks * 8;
                const __nv_bfloat16* r0 = A0 + k0;
                const __nv_bfloat16* r1 = r0 + 8 * APITCH;
                unsigned a[4];
                a[0] = f2u(__bfloat162float(r0[tg]));
                a[1] = f2u(__bfloat162float(r1[tg]));
                a[2] = f2u(__bfloat162float(r0[tg + 4]));
                a[3] = f2u(__bfloat162float(r1[tg + 4]));
                #pragma unroll
                for (int nt = 0; nt < 4; nt++) {
                    const float* bp = Bb + nt * 8 * BPITCH + k0;
                    mma_tf32(acc[nt], a, f2u(bp[tg]), f2u(bp[tg + 4]));
                }
            }
            asm volatile("cp.async.wait_group 0;\n");    // chunk1 + x landed
            __syncthreads();
            #pragma unroll 4
            for (int ks = 32; ks < 64; ks++) {
                const int k0 = ks * 8;
                const __nv_bfloat16* r0 = A0 + k0;
                const __nv_bfloat16* r1 = r0 + 8 * APITCH;
                unsigned a[4];
                a[0] = f2u(__bfloat162float(r0[tg]));
                a[1] = f2u(__bfloat162float(r1[tg]));
                a[2] = f2u(__bfloat162float(r0[tg + 4]));
                a[3] = f2u(__bfloat162float(r1[tg + 4]));
                #pragma unroll
                for (int nt = 0; nt < 4; nt++) {
                    const float* bp = Bb + nt * 8 * BPITCH + k0;
                    mma_tf32(acc[nt], a, f2u(bp[tg]), f2u(bp[tg + 4]));
                }
            }
        } else {
            asm volatile("cp.async.wait_group 0;\n");    // h0 = 0: gates = x-proj only
            __syncthreads();
        }

        // ---- Epilogue: all 4 gates local to this thread -> c/h update, packed bf16x2 store ----
        #pragma unroll
        for (int half = 0; half < 2; half++) {
            const int rloc = band + g4 + half * 8;
            const int grow = rowBase + rloc;
            __nv_bfloat16 hv[2];
            #pragma unroll
            for (int bb = 0; bb < 2; bb++) {
                const int e = half * 2 + bb;
                const int j = 2 * tg + bb;
                float xs[4];
                #pragma unroll
                for (int gate = 0; gate < 4; gate++) {
                    const int n = gate * 8 + j;
                    float s = sbias[n];
                    #pragma unroll
                    for (int i = 0; i < INDIM; i++) s += sx[rloc * INDIM + i] * swih[n * INDIM + i];
                    xs[gate] = s;
                }
                float iv = acc[0][e] + xs[0];
                float fv = acc[1][e] + xs[1];
                float gv = acc[2][e] + xs[2];
                float ov = acc[3][e] + xs[3];
                float cn = sigmf_(fv) * c_reg[half][bb] + sigmf_(iv) * tanhf(gv);
                c_reg[half][bb] = cn;
                hv[bb] = __float2bfloat16(sigmf_(ov) * tanhf(cn));
            }
            __nv_bfloat162 pack;
            pack.x = hv[0]; pack.y = hv[1];
            *(__nv_bfloat162*)(hout + (size_t)grow * HID + jBase + 2 * tg) = pack;
        }

        // ---- Grid barrier (128 CTAs all co-resident: grid <= SM count, 1 CTA/SM) ----
        __threadfence();
        __syncthreads();
        if (tid == 0) {
            unsigned old = atomicAdd(&g_arrive, 1u);
            if (old == GRID - 1) {
                atomicExch(&g_arrive, 0u);
                __threadfence();
                atomicAdd(&g_gen, 1u);
            } else {
                const unsigned target = (unsigned)(t + 1);
                unsigned g;
                do {
                    asm volatile("ld.acquire.gpu.u32 %0, [%1];" : "=r"(g) : "l"(&g_gen));
                } while (g < target);
            }
        }
        __syncthreads();
    }

    // ---- Fused head: CTA bx handles batch rows 2*bx, 2*bx+1. Final h is in g_h[0]
    //      (t=249 writes buf (1^1)=0). Read with L1-bypass for coherence. ----
    __syncthreads();
    float* red = (float*)sx;                              // reuse scratch
    {
        const int r = (blockIdx.x << 1) + (tid >> 7);
        const int cb = (tid & 127) * 4;
        const __nv_bfloat16* hp = g_h[0] + (size_t)r * HID + cb;
        uint2 v = __ldcg((const uint2*)hp);
        __nv_bfloat162 p0 = *reinterpret_cast<__nv_bfloat162*>(&v.x);
        __nv_bfloat162 p1 = *reinterpret_cast<__nv_bfloat162*>(&v.y);
        float s = __bfloat162float(p0.x) * W_out[cb]
                + __bfloat162float(p0.y) * W_out[cb + 1]
                + __bfloat162float(p1.x) * W_out[cb + 2]
                + __bfloat162float(p1.y) * W_out[cb + 3];
        #pragma unroll
        for (int o = 16; o; o >>= 1) s += __shfl_xor_sync(0xffffffffu, s, o);
        if (lane == 0) red[warp] = s;
    }
    __syncthreads();
    if (tid < 2) {
        float s = red[tid * 4] + red[tid * 4 + 1] + red[tid * 4 + 2] + red[tid * 4 + 3] + b_out[0];
        float lr = s > 0.0f ? s : 0.1f * s;
        out[(blockIdx.x << 1) + tid] = 1.0f / (1.0f + expf(-lr));
    }
}

extern "C" void kernel_launch(void* const* d_in, const int* in_sizes, int n_in,
                              void* d_out, int out_size) {
    const float* strokes = (const float*)d_in[0];
    const float* W_ih    = (const float*)d_in[1];
    const float* W_hh    = (const float*)d_in[2];
    const float* b_ih    = (const float*)d_in[3];
    const float* b_hh    = (const float*)d_in[4];
    const float* W_out   = (const float*)d_in[5];
    const float* b_out   = (const float*)d_in[6];
    float* out = (float*)d_out;

    cudaFuncSetAttribute(lstm_persistent_kernel,
                         cudaFuncAttributeMaxDynamicSharedMemorySize, SMEM_BYTES);

    init_kernel<<<1, 1>>>();
    lstm_persistent_kernel<<<GRID, NT, SMEM_BYTES>>>(
        strokes, W_ih, W_hh, b_ih, b_hh, W_out, b_out, out);
}

// round 11
// speedup vs baseline: 1.5049x; 1.0245x over previous
#include <cuda_runtime.h>
#include <cuda_bf16.h>
#include <cstdint>

// Problem dims
#define BATCH 256
#define HID   512
#define SEQ   250
#define INDIM 5

// Persistent tiling: 128 CTAs = 2 batch groups (M=128) x 64 hidden slices (HC=8 -> N=32 gate cols)
#define GRID  128
#define NT    256          // 8 warps; each warp owns one m16 band, all 4 n8 tiles
#define HC 8
#define NC 32              // 4 gates * HC

// SMEM pitches (bf16 elements). 520*2B = 1040B, 1040 mod 128 = 16 -> ldmatrix conflict-free
#define APITCH 520
#define BP     520

#define SA_BYTES  (128 * APITCH * 2)           // 133120
#define SBH_BYTES (NC * BP * 2)                // 33280 (W_hh hi)
#define SBL_BYTES (NC * BP * 2)                // 33280 (W_hh lo)
#define SX_BYTES  (128 * INDIM * 4)            // 2560
#define SWIH_BYTES (NC * INDIM * 4)            // 640
#define SBIAS_BYTES (NC * 4)                   // 128
#define SMEM_BYTES (SA_BYTES + SBH_BYTES + SBL_BYTES + SX_BYTES + SWIH_BYTES + SBIAS_BYTES)

// Persistent state (device globals: no allocation in kernel_launch)
__device__ __nv_bfloat16 g_h[2][BATCH * HID];
__device__ unsigned g_arrive;
__device__ unsigned g_gen;

__device__ __forceinline__ float sigmf_(float x) { return 1.0f / (1.0f + expf(-x)); }

__device__ __forceinline__ void mma_bf16(float* c, const unsigned* a, unsigned b0, unsigned b1) {
    asm volatile(
        "mma.sync.aligned.m16n8k16.row.col.f32.bf16.bf16.f32 "
        "{%0,%1,%2,%3}, {%4,%5,%6,%7}, {%8,%9}, {%0,%1,%2,%3};"
        : "+f"(c[0]), "+f"(c[1]), "+f"(c[2]), "+f"(c[3])
        : "r"(a[0]), "r"(a[1]), "r"(a[2]), "r"(a[3]), "r"(b0), "r"(b1));
}

__device__ __forceinline__ void ldsm_x4(unsigned& r0, unsigned& r1, unsigned& r2, unsigned& r3,
                                        uint32_t addr) {
    asm volatile("ldmatrix.sync.aligned.m8n8.x4.shared.b16 {%0,%1,%2,%3}, [%4];"
                 : "=r"(r0), "=r"(r1), "=r"(r2), "=r"(r3) : "r"(addr));
}

// cp.async: .cg (L1-bypass) for h tiles — required for cross-SM coherence of ping-pong h.
__device__ __forceinline__ void cp_async16(uint32_t dst, const void* src) {
    asm volatile("cp.async.cg.shared.global [%0], [%1], 16;\n" :: "r"(dst), "l"(src));
}
__device__ __forceinline__ void cp_async4(uint32_t dst, const void* src) {
    asm volatile("cp.async.ca.shared.global [%0], [%1], 4;\n" :: "r"(dst), "l"(src));
}
__device__ __forceinline__ void cp_commit() { asm volatile("cp.async.commit_group;\n"); }
template <int N> __device__ __forceinline__ void cp_wait() {
    asm volatile("cp.async.wait_group %0;\n" :: "n"(N));
}

__global__ void init_kernel() {
    g_arrive = 0u;
    g_gen = 0u;
}

__global__ __launch_bounds__(NT)
void lstm_persistent_kernel(const float* __restrict__ strokes,
                            const float* __restrict__ W_ih,
                            const float* __restrict__ W_hh,
                            const float* __restrict__ b_ih,
                            const float* __restrict__ b_hh,
                            const float* __restrict__ W_out,
                            const float* __restrict__ b_out,
                            float* __restrict__ out) {
    extern __shared__ char smem[];
    __nv_bfloat16* sA    = (__nv_bfloat16*)smem;                           // [128][APITCH] h tile
    __nv_bfloat16* sBh   = (__nv_bfloat16*)(smem + SA_BYTES);              // [32][BP] W_hh hi
    __nv_bfloat16* sBl   = (__nv_bfloat16*)(smem + SA_BYTES + SBH_BYTES);  // [32][BP] W_hh lo
    float*         sx    = (float*)(smem + SA_BYTES + SBH_BYTES + SBL_BYTES);  // [128][5]
    float*         swih  = sx + 128 * INDIM;                               // [32][5]
    float*         sbias = swih + NC * INDIM;                              // [32]

    const int tid = threadIdx.x;
    const int q = blockIdx.x & 63;
    const int p = blockIdx.x >> 6;
    const int rowBase = p * 128;
    const int jBase = q * HC;

    // ---- One-time: W_hh slice -> bf16 hi/lo, W_ih slice, fused biases ----
    #pragma unroll
    for (int it = 0; it < 16; it++) {
        int idx = tid + it * NT;                        // 4096 float4 total (32 rows x 128)
        int n = idx >> 7, c = idx & 127;
        int gate = n >> 3, j = n & 7;
        const float4* src = (const float4*)(W_hh + (size_t)(gate * HID + jBase + j) * HID);
        float4 v = src[c];
        __nv_bfloat16 h0 = __float2bfloat16(v.x), h1 = __float2bfloat16(v.y);
        __nv_bfloat16 h2 = __float2bfloat16(v.z), h3 = __float2bfloat16(v.w);
        __nv_bfloat16* dh = sBh + n * BP + c * 4;
        __nv_bfloat16* dl = sBl + n * BP + c * 4;
        dh[0] = h0; dh[1] = h1; dh[2] = h2; dh[3] = h3;
        dl[0] = __float2bfloat16(v.x - __bfloat162float(h0));
        dl[1] = __float2bfloat16(v.y - __bfloat162float(h1));
        dl[2] = __float2bfloat16(v.z - __bfloat162float(h2));
        dl[3] = __float2bfloat16(v.w - __bfloat162float(h3));
    }
    if (tid < NC) {
        int gate = tid >> 3, j = tid & 7;
        int gr = gate * HID + jBase + j;
        sbias[tid] = b_ih[gr] + b_hh[gr];
        #pragma unroll
        for (int i = 0; i < INDIM; i++) swih[tid * INDIM + i] = W_ih[gr * INDIM + i];
    }
    __syncthreads();

    const uint32_t sa_base  = (uint32_t)__cvta_generic_to_shared(sA);
    const uint32_t sbh_base = (uint32_t)__cvta_generic_to_shared(sBh);
    const uint32_t sbl_base = (uint32_t)__cvta_generic_to_shared(sBl);
    const uint32_t sx_base  = (uint32_t)__cvta_generic_to_shared(sx);

    const int warp = tid >> 5, lane = tid & 31;
    const int g4 = lane >> 2, tg = lane & 3;
    const int band = warp * 16;                          // this warp's m16 band

    // ldmatrix lane-address bases (byte offsets into smem space)
    const int lg = lane >> 3, lr = lane & 7;
    // A tiles: T0=(m0-7,k0) T1=(m8-15,k0) T2=(m0-7,k8) T3=(m8-15,k8)
    const uint32_t aAddr0 = sa_base +
        (uint32_t)((band + (lg & 1) * 8 + lr) * APITCH + (lg >> 1) * 8) * 2;
    // B tiles: T0=(n0-7,k0) T1=(n0-7,k8) T2=(n8-15,k0) T3=(n8-15,k8)
    const uint32_t bOff = (uint32_t)(((lg >> 1) * 8 + lr) * BP + (lg & 1) * 8) * 2;
    const uint32_t bhAddr0 = sbh_base + bOff;            // n-tiles 0,1
    const uint32_t bhAddr1 = sbh_base + (uint32_t)(16 * BP * 2) + bOff;  // n-tiles 2,3
    const uint32_t blAddr0 = sbl_base + bOff;
    const uint32_t blAddr1 = sbl_base + (uint32_t)(16 * BP * 2) + bOff;

    // c state in registers: thread owns (row = band+g4+8*half, j = 2*tg+bb)
    float c_reg[2][2] = {{0.0f, 0.0f}, {0.0f, 0.0f}};

    for (int t = 0; t < SEQ; ++t) {
        const __nv_bfloat16* __restrict__ hin = g_h[t & 1] + rowBase * HID;
        __nv_bfloat16* __restrict__ hout = g_h[(t & 1) ^ 1];

        // ---- Issue x tile (group 0), then 4 A k-chunks (groups 1..4) ----
        for (int idx = tid; idx < 128 * INDIM; idx += NT) {
            int r = idx / INDIM, i = idx - r * INDIM;
            cp_async4(sx_base + (uint32_t)idx * 4,
                      strokes + (size_t)(rowBase + r) * (SEQ * INDIM) + t * INDIM + i);
        }
        cp_commit();
        if (t > 0) {
            const uint4* hin4 = (const uint4*)hin;       // [128 rows][64 uint4] (512 bf16/row)
            #pragma unroll
            for (int ch = 0; ch < 4; ch++) {
                // chunk ch = k-quarter: 128 rows x 16 uint4 = 2048 transfers -> 8 iters at NT=256
                #pragma unroll
                for (int it = 0; it < 8; it++) {
                    int idx = tid + it * NT;             // 0..2047
                    int r = idx >> 4;                    // 0..127
                    int cq = (idx & 15) + ch * 16;       // 0..63 (uint4 col within row)
                    cp_async16(sa_base + (uint32_t)(r * APITCH + cq * 8) * 2,
                               hin4 + r * 64 + cq);
                }
                cp_commit();
            }
            cp_wait<4>();                                // x landed
        } else {
            cp_wait<0>();
        }
        __syncthreads();

        // ---- x-projection into registers (hidden under A-chunk latency) ----
        float xs[2][2][4];
        #pragma unroll
        for (int half = 0; half < 2; half++) {
            const int rloc = band + g4 + half * 8;
            float xv[INDIM];
            #pragma unroll
            for (int i = 0; i < INDIM; i++) xv[i] = sx[rloc * INDIM + i];
            #pragma unroll
            for (int bb = 0; bb < 2; bb++) {
                const int j = 2 * tg + bb;
                #pragma unroll
                for (int gate = 0; gate < 4; gate++) {
                    const int n = gate * 8 + j;
                    float s = sbias[n];
                    #pragma unroll
                    for (int i = 0; i < INDIM; i++) s += xv[i] * swih[n * INDIM + i];
                    xs[half][bb][gate] = s;
                }
            }
        }

        float acc[4][4];
        #pragma unroll
        for (int a = 0; a < 4; a++)
            #pragma unroll
            for (int b = 0; b < 4; b++) acc[a][b] = 0.0f;

        if (t > 0) {
            // ---- MMA over 4 progressively-arriving k-chunks ----
            #pragma unroll
            for (int ch = 0; ch < 4; ch++) {
                switch (ch) {                             // wait_group needs an immediate
                    case 0: cp_wait<3>(); break;
                    case 1: cp_wait<2>(); break;
                    case 2: cp_wait<1>(); break;
                    default: cp_wait<0>(); break;
                }
                __syncthreads();
                #pragma unroll
                for (int i = 0; i < 8; i++) {
                    const uint32_t kb = (uint32_t)(ch * 128 + i * 16) * 2;  // byte offset
                    unsigned a[4], bh0[4], bh1[4], bl0[4], bl1[4];
                    ldsm_x4(a[0], a[1], a[2], a[3], aAddr0 + kb);
                    ldsm_x4(bh0[0], bh0[1], bh0[2], bh0[3], bhAddr0 + kb);
                    ldsm_x4(bh1[0], bh1[1], bh1[2], bh1[3], bhAddr1 + kb);
                    ldsm_x4(bl0[0], bl0[1], bl0[2], bl0[3], blAddr0 + kb);
                    ldsm_x4(bl1[0], bl1[1], bl1[2], bl1[3], blAddr1 + kb);
                    mma_bf16(acc[0], a, bh0[0], bh0[1]);
                    mma_bf16(acc[1], a, bh0[2], bh0[3]);
                    mma_bf16(acc[2], a, bh1[0], bh1[1]);
                    mma_bf16(acc[3], a, bh1[2], bh1[3]);
                    mma_bf16(acc[0], a, bl0[0], bl0[1]);
                    mma_bf16(acc[1], a, bl0[2], bl0[3]);
                    mma_bf16(acc[2], a, bl1[0], bl1[1]);
                    mma_bf16(acc[3], a, bl1[2], bl1[3]);
                }
            }
        }

        // ---- Epilogue: gates -> c/h update (c in regs), packed bf16x2 h store ----
        // C frag (m16n8): e0=(g4,2tg) e1=(g4,2tg+1) e2=(g4+8,2tg) e3=(g4+8,2tg+1)
        #pragma unroll
        for (int half = 0; half < 2; half++) {
            const int grow = rowBase + band + g4 + half * 8;
            __nv_bfloat16 hv[2];
            #pragma unroll
            for (int bb = 0; bb < 2; bb++) {
                const int e = half * 2 + bb;
                float iv = acc[0][e] + xs[half][bb][0];
                float fv = acc[1][e] + xs[half][bb][1];
                float gv = acc[2][e] + xs[half][bb][2];
                float ov = acc[3][e] + xs[half][bb][3];
                float cn = sigmf_(fv) * c_reg[half][bb] + sigmf_(iv) * tanhf(gv);
                c_reg[half][bb] = cn;
                hv[bb] = __float2bfloat16(sigmf_(ov) * tanhf(cn));
            }
            __nv_bfloat162 pack;
            pack.x = hv[0]; pack.y = hv[1];
            *(__nv_bfloat162*)(hout + (size_t)grow * HID + jBase + 2 * tg) = pack;
        }

        // ---- Grid barrier (128 CTAs co-resident: 1 CTA/SM) ----
        __threadfence();
        __syncthreads();
        if (tid == 0) {
            unsigned old = atomicAdd(&g_arrive, 1u);
            if (old == GRID - 1) {
                atomicExch(&g_arrive, 0u);
                __threadfence();
                atomicAdd(&g_gen, 1u);
            } else {
                const unsigned target = (unsigned)(t + 1);
                unsigned g;
                do {
                    asm volatile("ld.acquire.gpu.u32 %0, [%1];" : "=r"(g) : "l"(&g_gen));
                } while (g < target);
            }
        }
        __syncthreads();
    }

    // ---- Fused head: CTA bx -> batch rows 2bx, 2bx+1. Final h in g_h[0] (SEQ even). ----
    __syncthreads();
    float* red = (float*)sx;
    {
        const int r = (blockIdx.x << 1) + (tid >> 7);
        const int cb = (tid & 127) * 4;
        const __nv_bfloat16* hp = g_h[0] + (size_t)r * HID + cb;
        uint2 v = __ldcg((const uint2*)hp);              // L1-bypass for coherence
        __nv_bfloat162 p0 = *reinterpret_cast<__nv_bfloat162*>(&v.x);
        __nv_bfloat162 p1 = *reinterpret_cast<__nv_bfloat162*>(&v.y);
        float s = __bfloat162float(p0.x) * W_out[cb]
                + __bfloat162float(p0.y) * W_out[cb + 1]
                + __bfloat162float(p1.x) * W_out[cb + 2]
                + __bfloat162float(p1.y) * W_out[cb + 3];
        #pragma unroll
        for (int o = 16; o; o >>= 1) s += __shfl_xor_sync(0xffffffffu, s, o);
        if (lane == 0) red[warp] = s;
    }
    __syncthreads();
    if (tid < 2) {
        float s = red[tid * 4] + red[tid * 4 + 1] + red[tid * 4 + 2] + red[tid * 4 + 3] + b_out[0];
        float lr = s > 0.0f ? s : 0.1f * s;
        out[(blockIdx.x << 1) + tid] = 1.0f / (1.0f + expf(-lr));
    }
}

extern "C" void kernel_launch(void* const* d_in, const int* in_sizes, int n_in,
                              void* d_out, int out_size) {
    const float* strokes = (const float*)d_in[0];
    const float* W_ih    = (const float*)d_in[1];
    const float* W_hh    = (const float*)d_in[2];
    const float* b_ih    = (const float*)d_in[3];
    const float* b_hh    = (const float*)d_in[4];
    const float* W_out   = (const float*)d_in[5];
    const float* b_out   = (const float*)d_in[6];
    float* out = (float*)d_out;

    cudaFuncSetAttribute(lstm_persistent_kernel,
                         cudaFuncAttributeMaxDynamicSharedMemorySize, SMEM_BYTES);

    init_kernel<<<1, 1>>>();
    lstm_persistent_kernel<<<GRID, NT, SMEM_BYTES>>>(
        strokes, W_ih, W_hh, b_ih, b_hh, W_out, b_out, out);
}